// round 9
// baseline (speedup 1.0000x reference)
#include <cuda_runtime.h>

#define WIDTH  1024
#define HEIGHT 1024
#define RPB    8          // rows per block-strip (must divide HEIGHT)

// Global accumulator state. Self-resetting: returns to {0,0} at the end of
// every launch, so each call (and each graph replay) does identical work.
__device__ double       g_sum   = 0.0;
__device__ unsigned int g_count = 0;

struct RowData {
    float4 v;      // 4 target values at columns c..c+3
    float  hl, hr; // column halo (c-1 clamped, c+4 clamped)
};

__device__ __forceinline__ RowData load_row(const float* __restrict__ r,
                                            int c, int cl, int cr)
{
    RowData d;
    d.v  = *reinterpret_cast<const float4*>(r + c);
    d.hl = r[cl];
    d.hr = r[cr];
    return d;
}

// EXACT R2 streaming body (proven ~6.4 TB/s). Each block handles an 8-row
// strip of one image; the 3-row target window rolls through registers.
// Binary-mask morphology: boundary <=> clamped 3x3 window sum in (0,9).
// BCE with t in {0,1}: bce = -log(t ? p : 1-p)  -> one __logf per pixel.
//
// Reduction: each block's leader atomically adds its double partial into
// g_sum while streaming continues on other SMs (single-lane L2 atomics,
// fully hidden). The LAST block only reads the finished sum and writes the
// output -- no partials array, no tree, no second kernel launch.
__global__ void __launch_bounds__(256)
loss_kernel(const float* __restrict__ pred, const float* __restrict__ tgt,
            float* __restrict__ out, int n_strips, double inv_n)
{
    const int strip = blockIdx.x;
    const int row0  = strip * RPB;
    const int y0    = row0 & (HEIGHT - 1);   // strip never crosses images

    const int c  = threadIdx.x << 2;
    const int cl = (c == 0) ? 0 : c - 1;
    const int cr = (c + 4 >= WIDTH) ? (WIDTH - 1) : (c + 4);

    const float* tbase = tgt  + (size_t)row0 * WIDTH;
    const float* pbase = pred + (size_t)row0 * WIDTH;

    RowData a_prev = load_row((y0 == 0) ? tbase : tbase - WIDTH, c, cl, cr);
    RowData a_cur  = load_row(tbase, c, cl, cr);

    float acc = 0.0f;    // accumulates +w*log(arg); negated at the end

    #pragma unroll
    for (int i = 0; i < RPB; i++) {
        const int y = y0 + i;
        const float* trow_next = (y == HEIGHT - 1) ? tbase + (size_t)i * WIDTH
                                                   : tbase + (size_t)(i + 1) * WIDTH;
        const RowData a_next = load_row(trow_next, c, cl, cr);
        const float4  p = *reinterpret_cast<const float4*>(
                              pbase + (size_t)i * WIDTH + c);

        const float v0 = a_prev.v.x + a_cur.v.x + a_next.v.x;
        const float v1 = a_prev.v.y + a_cur.v.y + a_next.v.y;
        const float v2 = a_prev.v.z + a_cur.v.z + a_next.v.z;
        const float v3 = a_prev.v.w + a_cur.v.w + a_next.v.w;
        const float vl = a_prev.hl  + a_cur.hl  + a_next.hl;
        const float vr = a_prev.hr  + a_cur.hr  + a_next.hr;

        const float s0 = vl + v0 + v1;
        const float s1 = v0 + v1 + v2;
        const float s2 = v1 + v2 + v3;
        const float s3 = v2 + v3 + vr;

#define PIX(S, T, P)                                                      \
        do {                                                              \
            const float arg = ((T) > 0.5f) ? (P) : (1.0f - (P));          \
            const float w   = ((S) > 0.5f && (S) < 8.5f) ? 3.0f : 1.0f;   \
            acc = fmaf(w, __logf(arg), acc);                              \
        } while (0)

        PIX(s0, a_cur.v.x, p.x);
        PIX(s1, a_cur.v.y, p.y);
        PIX(s2, a_cur.v.z, p.z);
        PIX(s3, a_cur.v.w, p.w);
#undef PIX

        a_prev = a_cur;
        a_cur  = a_next;
    }

    // Block reduction: warp shuffle, then 8 warp leaders through smem.
    #pragma unroll
    for (int o = 16; o > 0; o >>= 1)
        acc += __shfl_xor_sync(0xffffffffu, acc, o);

    __shared__ float sacc[8];
    const int wid  = threadIdx.x >> 5;
    const int lane = threadIdx.x & 31;
    if (lane == 0) sacc[wid] = acc;
    __syncthreads();

    if (threadIdx.x == 0) {
        float s = 0.0f;
        #pragma unroll
        for (int i = 0; i < 8; i++) s += sacc[i];

        // Contribute this block's partial (negated: loss = -sum w*log(arg)).
        atomicAdd(&g_sum, (double)(-s));
        __threadfence();                           // order sum-add before count-add
        const unsigned int old = atomicAdd(&g_count, 1u);
        if (old == (unsigned int)(n_strips - 1)) {
            // All sum-adds happened-before their count-adds; all counts seen.
            __threadfence();
            const double total = g_sum;
            out[0]  = (float)(total * inv_n);
            g_sum   = 0.0;                         // reset for next replay
            __threadfence();
            g_count = 0;
        }
    }
}

extern "C" void kernel_launch(void* const* d_in, const int* in_sizes, int n_in,
                              void* d_out, int out_size)
{
    const float* pred = (const float*)d_in[0];
    const float* tgt  = (const float*)d_in[1];
    const int n      = in_sizes[0];        // B*1*H*W
    const int rows   = n / WIDTH;          // B*H
    const int strips = rows / RPB;

    loss_kernel<<<strips, 256>>>(pred, tgt, (float*)d_out, strips,
                                 1.0 / (double)n);
}

// round 10
// speedup vs baseline: 1.0261x; 1.0261x over previous
#include <cuda_runtime.h>

#define WIDTH  1024
#define HEIGHT 1024
#define RPB    8          // rows per block-strip (must divide HEIGHT)

// One partial per block-strip. 32*1024/8 = 4096 for the nominal shape.
__device__ float g_partials[65536];

struct RowData {
    float4 v;      // 4 target values at columns c..c+3
    float  hl, hr; // column halo (c-1 clamped, c+4 clamped)
};

__device__ __forceinline__ RowData load_row(const float* __restrict__ r,
                                            int c, int cl, int cr)
{
    RowData d;
    d.v  = *reinterpret_cast<const float4*>(r + c);
    d.hl = r[cl];
    d.hr = r[cr];
    return d;
}

// EXACT R2 streaming body (best measured: ~44us, ~6.4 TB/s).
// Binary-mask morphology: boundary <=> clamped 3x3 window sum in (0,9).
// BCE with t in {0,1}: bce = -log(t ? p : 1-p)  -> one __logf per pixel.
__global__ void __launch_bounds__(256)
loss_kernel(const float* __restrict__ pred, const float* __restrict__ tgt)
{
    const int strip = blockIdx.x;
    const int row0  = strip * RPB;
    const int y0    = row0 & (HEIGHT - 1);   // strip never crosses images

    const int c  = threadIdx.x << 2;
    const int cl = (c == 0) ? 0 : c - 1;
    const int cr = (c + 4 >= WIDTH) ? (WIDTH - 1) : (c + 4);

    const float* tbase = tgt  + (size_t)row0 * WIDTH;
    const float* pbase = pred + (size_t)row0 * WIDTH;

    RowData a_prev = load_row((y0 == 0) ? tbase : tbase - WIDTH, c, cl, cr);
    RowData a_cur  = load_row(tbase, c, cl, cr);

    float acc = 0.0f;    // accumulates +w*log(arg); negated at the end

    #pragma unroll
    for (int i = 0; i < RPB; i++) {
        const int y = y0 + i;
        const float* trow_next = (y == HEIGHT - 1) ? tbase + (size_t)i * WIDTH
                                                   : tbase + (size_t)(i + 1) * WIDTH;
        const RowData a_next = load_row(trow_next, c, cl, cr);
        const float4  p = *reinterpret_cast<const float4*>(
                              pbase + (size_t)i * WIDTH + c);

        const float v0 = a_prev.v.x + a_cur.v.x + a_next.v.x;
        const float v1 = a_prev.v.y + a_cur.v.y + a_next.v.y;
        const float v2 = a_prev.v.z + a_cur.v.z + a_next.v.z;
        const float v3 = a_prev.v.w + a_cur.v.w + a_next.v.w;
        const float vl = a_prev.hl  + a_cur.hl  + a_next.hl;
        const float vr = a_prev.hr  + a_cur.hr  + a_next.hr;

        const float s0 = vl + v0 + v1;
        const float s1 = v0 + v1 + v2;
        const float s2 = v1 + v2 + v3;
        const float s3 = v2 + v3 + vr;

#define PIX(S, T, P)                                                      \
        do {                                                              \
            const float arg = ((T) > 0.5f) ? (P) : (1.0f - (P));          \
            const float w   = ((S) > 0.5f && (S) < 8.5f) ? 3.0f : 1.0f;   \
            acc = fmaf(w, __logf(arg), acc);                              \
        } while (0)

        PIX(s0, a_cur.v.x, p.x);
        PIX(s1, a_cur.v.y, p.y);
        PIX(s2, a_cur.v.z, p.z);
        PIX(s3, a_cur.v.w, p.w);
#undef PIX

        a_prev = a_cur;
        a_cur  = a_next;
    }

    // Block reduction: warp shuffle, then 8 warp leaders through smem.
    #pragma unroll
    for (int o = 16; o > 0; o >>= 1)
        acc += __shfl_xor_sync(0xffffffffu, acc, o);

    __shared__ float sacc[8];
    const int wid  = threadIdx.x >> 5;
    const int lane = threadIdx.x & 31;
    if (lane == 0) sacc[wid] = acc;
    __syncthreads();
    if (threadIdx.x == 0) {
        float s = 0.0f;
        #pragma unroll
        for (int i = 0; i < 8; i++) s += sacc[i];
        g_partials[strip] = -s;
    }
}

// Deterministic finalize, launched with PROGRAMMATIC DEPENDENT LAUNCH:
// this block is scheduled while loss_kernel still streams, runs its prelude,
// then blocks in cudaGridDependencySynchronize() until loss_kernel completes
// (which makes all g_partials writes visible). Removes the ~7us inter-node
// launch gap; only the ~1us of real reduction work remains serialized.
__global__ void __launch_bounds__(256)
finalize_kernel(float* __restrict__ out, int n_part, double inv_n)
{
    cudaGridDependencySynchronize();

    const int n4 = n_part >> 2;   // n_part divisible by 4
    double s0 = 0.0, s1 = 0.0;
    for (int i = threadIdx.x; i < n4; i += 256) {
        const float4 v = reinterpret_cast<const float4*>(g_partials)[i];
        s0 += (double)v.x + (double)v.y;
        s1 += (double)v.z + (double)v.w;
    }
    double s = s0 + s1;

    // Warp reduction in double, then 8 warp leaders.
    #pragma unroll
    for (int o = 16; o > 0; o >>= 1)
        s += __shfl_xor_sync(0xffffffffu, s, o);

    __shared__ double sd[8];
    const int wid  = threadIdx.x >> 5;
    const int lane = threadIdx.x & 31;
    if (lane == 0) sd[wid] = s;
    __syncthreads();
    if (threadIdx.x == 0) {
        double t = 0.0;
        #pragma unroll
        for (int i = 0; i < 8; i++) t += sd[i];
        out[0] = (float)(t * inv_n);
    }
}

extern "C" void kernel_launch(void* const* d_in, const int* in_sizes, int n_in,
                              void* d_out, int out_size)
{
    const float* pred = (const float*)d_in[0];
    const float* tgt  = (const float*)d_in[1];
    const int n      = in_sizes[0];        // B*1*H*W
    const int rows   = n / WIDTH;          // B*H
    const int strips = rows / RPB;

    loss_kernel<<<strips, 256>>>(pred, tgt);

    // Finalize with programmatic stream serialization (PDL): overlap its
    // launch/scheduling with the tail of loss_kernel.
    cudaLaunchConfig_t cfg = {};
    cfg.gridDim  = dim3(1, 1, 1);
    cfg.blockDim = dim3(256, 1, 1);
    cfg.dynamicSmemBytes = 0;
    cfg.stream = 0;   // same (legacy default) stream as the <<<>>> launch above
    cudaLaunchAttribute attrs[1];
    attrs[0].id = cudaLaunchAttributeProgrammaticStreamSerialization;
    attrs[0].val.programmaticStreamSerializationAllowed = 1;
    cfg.attrs    = attrs;
    cfg.numAttrs = 1;

    float*  out   = (float*)d_out;
    double  inv_n = 1.0 / (double)n;
    cudaLaunchKernelEx(&cfg, finalize_kernel, out, strips, inv_n);
}

// round 11
// speedup vs baseline: 1.0338x; 1.0075x over previous
#include <cuda_runtime.h>

#define WIDTH  1024
#define HEIGHT 1024
#define RPB    16         // rows per block-strip (must divide HEIGHT)

// One partial per block-strip. 32*1024/16 = 2048 for the nominal shape.
__device__ float g_partials[65536];

struct RowData {
    float4 v;      // 4 target values at columns c..c+3
    float  hl, hr; // column halo (c-1 clamped, c+4 clamped)
};

__device__ __forceinline__ RowData load_row(const float* __restrict__ r,
                                            int c, int cl, int cr)
{
    RowData d;
    d.v  = *reinterpret_cast<const float4*>(r + c);
    d.hl = r[cl];
    d.hr = r[cr];
    return d;
}

// R2 streaming body, RPB=16 (halo overhead 1.125x vs 1.25x, traffic
// 288MB -> 272MB). No cache hints, no reg caps, no shuffle halos, no fusion:
// those each regressed independently in R3/R4/R5/R7/R9.
// Binary-mask morphology: boundary <=> clamped 3x3 window sum in (0,9).
// BCE with t in {0,1}: bce = -log(t ? p : 1-p)  -> one __logf per pixel.
__global__ void __launch_bounds__(256)
loss_kernel(const float* __restrict__ pred, const float* __restrict__ tgt)
{
    const int strip = blockIdx.x;
    const int row0  = strip * RPB;
    const int y0    = row0 & (HEIGHT - 1);   // strip never crosses images

    const int c  = threadIdx.x << 2;
    const int cl = (c == 0) ? 0 : c - 1;
    const int cr = (c + 4 >= WIDTH) ? (WIDTH - 1) : (c + 4);

    const float* tbase = tgt  + (size_t)row0 * WIDTH;
    const float* pbase = pred + (size_t)row0 * WIDTH;

    RowData a_prev = load_row((y0 == 0) ? tbase : tbase - WIDTH, c, cl, cr);
    RowData a_cur  = load_row(tbase, c, cl, cr);

    float acc = 0.0f;    // accumulates +w*log(arg); negated at the end

    #pragma unroll
    for (int i = 0; i < RPB; i++) {
        const int y = y0 + i;
        const float* trow_next = (y == HEIGHT - 1) ? tbase + (size_t)i * WIDTH
                                                   : tbase + (size_t)(i + 1) * WIDTH;
        const RowData a_next = load_row(trow_next, c, cl, cr);
        const float4  p = *reinterpret_cast<const float4*>(
                              pbase + (size_t)i * WIDTH + c);

        const float v0 = a_prev.v.x + a_cur.v.x + a_next.v.x;
        const float v1 = a_prev.v.y + a_cur.v.y + a_next.v.y;
        const float v2 = a_prev.v.z + a_cur.v.z + a_next.v.z;
        const float v3 = a_prev.v.w + a_cur.v.w + a_next.v.w;
        const float vl = a_prev.hl  + a_cur.hl  + a_next.hl;
        const float vr = a_prev.hr  + a_cur.hr  + a_next.hr;

        const float s0 = vl + v0 + v1;
        const float s1 = v0 + v1 + v2;
        const float s2 = v1 + v2 + v3;
        const float s3 = v2 + v3 + vr;

#define PIX(S, T, P)                                                      \
        do {                                                              \
            const float arg = ((T) > 0.5f) ? (P) : (1.0f - (P));          \
            const float w   = ((S) > 0.5f && (S) < 8.5f) ? 3.0f : 1.0f;   \
            acc = fmaf(w, __logf(arg), acc);                              \
        } while (0)

        PIX(s0, a_cur.v.x, p.x);
        PIX(s1, a_cur.v.y, p.y);
        PIX(s2, a_cur.v.z, p.z);
        PIX(s3, a_cur.v.w, p.w);
#undef PIX

        a_prev = a_cur;
        a_cur  = a_next;
    }

    // Block reduction: warp shuffle, then 8 warp leaders through smem.
    #pragma unroll
    for (int o = 16; o > 0; o >>= 1)
        acc += __shfl_xor_sync(0xffffffffu, acc, o);

    __shared__ float sacc[8];
    const int wid  = threadIdx.x >> 5;
    const int lane = threadIdx.x & 31;
    if (lane == 0) sacc[wid] = acc;
    __syncthreads();
    if (threadIdx.x == 0) {
        float s = 0.0f;
        #pragma unroll
        for (int i = 0; i < 8; i++) s += sacc[i];
        g_partials[strip] = -s;
    }
}

// Deterministic finalize with PROGRAMMATIC DEPENDENT LAUNCH: scheduled while
// loss_kernel still streams; blocks in cudaGridDependencySynchronize() until
// loss_kernel completes (all g_partials writes visible), then ~1us of work.
__global__ void __launch_bounds__(256)
finalize_kernel(float* __restrict__ out, int n_part, double inv_n)
{
    cudaGridDependencySynchronize();

    const int n4 = n_part >> 2;   // n_part divisible by 4
    double s0 = 0.0, s1 = 0.0;
    for (int i = threadIdx.x; i < n4; i += 256) {
        const float4 v = reinterpret_cast<const float4*>(g_partials)[i];
        s0 += (double)v.x + (double)v.y;
        s1 += (double)v.z + (double)v.w;
    }
    double s = s0 + s1;

    // Warp reduction in double, then 8 warp leaders.
    #pragma unroll
    for (int o = 16; o > 0; o >>= 1)
        s += __shfl_xor_sync(0xffffffffu, s, o);

    __shared__ double sd[8];
    const int wid  = threadIdx.x >> 5;
    const int lane = threadIdx.x & 31;
    if (lane == 0) sd[wid] = s;
    __syncthreads();
    if (threadIdx.x == 0) {
        double t = 0.0;
        #pragma unroll
        for (int i = 0; i < 8; i++) t += sd[i];
        out[0] = (float)(t * inv_n);
    }
}

extern "C" void kernel_launch(void* const* d_in, const int* in_sizes, int n_in,
                              void* d_out, int out_size)
{
    const float* pred = (const float*)d_in[0];
    const float* tgt  = (const float*)d_in[1];
    const int n      = in_sizes[0];        // B*1*H*W
    const int rows   = n / WIDTH;          // B*H
    const int strips = rows / RPB;

    loss_kernel<<<strips, 256>>>(pred, tgt);

    // Finalize with programmatic stream serialization (PDL).
    cudaLaunchConfig_t cfg = {};
    cfg.gridDim  = dim3(1, 1, 1);
    cfg.blockDim = dim3(256, 1, 1);
    cfg.dynamicSmemBytes = 0;
    cfg.stream = 0;
    cudaLaunchAttribute attrs[1];
    attrs[0].id = cudaLaunchAttributeProgrammaticStreamSerialization;
    attrs[0].val.programmaticStreamSerializationAllowed = 1;
    cfg.attrs    = attrs;
    cfg.numAttrs = 1;

    float*  out   = (float*)d_out;
    double  inv_n = 1.0 / (double)n;
    cudaLaunchKernelEx(&cfg, finalize_kernel, out, strips, inv_n);
}